// round 15
// baseline (speedup 1.0000x reference)
#include <cuda_runtime.h>
#include <math.h>

#define Nn 10000
#define Ee 160000
#define Ff 4
#define Hh 32
#define Cc 4

// ---------------- scratch (device globals; no allocation allowed) -----------
__device__ float g_Qn[Nn * Hh * Hh];       // per-node Q matrices [N, H, H] (40MB)
__device__ float g_r [Nn * Hh];            // per-node b2 contribution r[n,o]
__device__ float g_xA[Nn * Hh];            // ping-pong node features (pre-relu)
__device__ float g_xB[Nn * Hh];
__device__ int    g_cnt[Nn];               // counting sort: histogram
__device__ int    g_cur[Nn];               // counting sort: scatter cursors
__device__ int    g_off[Nn + 1];           // CSR offsets by src
__device__ int    g_sdst[Ee];              // dst sorted by src
__device__ float2 g_sea [Ee];              // edge_attr sorted by src

// ---------------------------------------------------------------------------
__global__ void zero_kernel() {
    int t = blockIdx.x * blockDim.x + threadIdx.x;
    if (t < Nn) { g_cnt[t] = 0; g_cur[t] = 0; }
}

__global__ void hist_kernel(const int* __restrict__ ei) {
    int base = (blockIdx.x * blockDim.x + threadIdx.x) * 4;
#pragma unroll
    for (int j = 0; j < 4; j++) {
        int t = base + j;
        if (t < Ee) atomicAdd(&g_cnt[ei[t]], 1);
    }
}

// warp-shfl scan: 1024 threads x 10 items, 2 barriers total
__global__ void scan_kernel() {
    __shared__ int wsum[32];
    const int tid  = threadIdx.x;
    const int lane = tid & 31, wid = tid >> 5;
    const int base = tid * 10;

    int loc[10];
    int s = 0;
#pragma unroll
    for (int j = 0; j < 10; j++) {
        int idx = base + j;
        int v = (idx < Nn) ? g_cnt[idx] : 0;
        loc[j] = s;
        s += v;
    }
    int t = s;
#pragma unroll
    for (int d = 1; d < 32; d <<= 1) {
        int u = __shfl_up_sync(0xffffffffu, t, d);
        if (lane >= d) t += u;
    }
    if (lane == 31) wsum[wid] = t;
    __syncthreads();
    if (wid == 0) {
        int w = wsum[lane];
#pragma unroll
        for (int d = 1; d < 32; d <<= 1) {
            int u = __shfl_up_sync(0xffffffffu, w, d);
            if (lane >= d) w += u;
        }
        wsum[lane] = w;
    }
    __syncthreads();
    int prefix = t - s + (wid > 0 ? wsum[wid - 1] : 0);
#pragma unroll
    for (int j = 0; j < 10; j++) {
        int idx = base + j;
        if (idx < Nn) g_off[idx] = prefix + loc[j];
    }
    if (tid == 1023) g_off[Nn] = wsum[31];
}

__global__ void scatter_kernel(const int* __restrict__ ei,
                               const float* __restrict__ ea) {
    int base = (blockIdx.x * blockDim.x + threadIdx.x) * 2;
#pragma unroll
    for (int j = 0; j < 2; j++) {
        int t = base + j;
        if (t < Ee) {
            int s = ei[t];
            int p = g_off[s] + atomicAdd(&g_cur[s], 1);
            g_sdst[p] = ei[Ee + t];
            g_sea[p]  = reinterpret_cast<const float2*>(ea)[t];
        }
    }
}

// ---------------------------------------------------------------------------
// layer-0 node init: agg = x·root + bias,  rbuf = x·b2   (din = 4)
// ---------------------------------------------------------------------------
__global__ void aux0_kernel(const float* __restrict__ x,
                            const float* __restrict__ root,
                            const float* __restrict__ bias,
                            const float* __restrict__ b2,
                            float* __restrict__ agg,
                            float* __restrict__ rbuf) {
    int warp = (blockIdx.x * blockDim.x + threadIdx.x) >> 5;
    int lane = threadIdx.x & 31;
    if (warp >= Nn) return;
    float accA = 0.f, accR = 0.f;
#pragma unroll
    for (int i = 0; i < Ff; i++) {
        float xv = x[warp * Ff + i];
        accA = fmaf(xv, root[i * Hh + lane], accA);
        accR = fmaf(xv, b2[i * Hh + lane], accR);
    }
    agg [warp * Hh + lane] = accA + bias[lane];
    rbuf[warp * Hh + lane] = accR;
}

// ---------------------------------------------------------------------------
// shared edge mainloop, SHFL-FREE: ea/dst tiles staged in per-warp smem,
// read back via broadcast LDS. Scalar qreg (32 regs) for 4-blocks/SM occ.
// ---------------------------------------------------------------------------
struct WarpTile {
    float  hs[32][32];    // h tile: [edge][k]
    float2 ea[32];        // staged edge attrs
    int    dst[32];       // staged dst ids
};

__device__ __forceinline__ void edge_loop(
    int beg, int end, int lane,
    float w1a, float w1b, float b1v,
    const float* qreg,               // [32]
    float rsrc,
    WarpTile* wt,
    float* __restrict__ agg)
{
    for (int t = beg; t < end; t += 32) {
        const int m = min(32, end - t);
        if (lane < m) {
            wt->ea [lane] = g_sea [t + lane];
            wt->dst[lane] = g_sdst[t + lane];
        }
        __syncwarp();

        // phase 1: h tile (lane = k), ea via broadcast LDS
        for (int e = 0; e < m; e++) {
            float2 eav = wt->ea[e];
            wt->hs[e][lane] = fmaxf(fmaf(eav.x, w1a, fmaf(eav.y, w1b, b1v)), 0.f);
        }
        __syncwarp();

        // phase 2: msg = r + Q^T h, dst via broadcast LDS
        for (int e = 0; e < m; e++) {
            int dst = wt->dst[e];
            const float4* hv = reinterpret_cast<const float4*>(wt->hs[e]);
            float a0 = rsrc, a1 = 0.f, a2 = 0.f, a3 = 0.f;
#pragma unroll
            for (int c = 0; c < 8; c++) {
                float4 h4 = hv[c];
                a0 = fmaf(h4.x, qreg[4 * c    ], a0);
                a1 = fmaf(h4.y, qreg[4 * c + 1], a1);
                a2 = fmaf(h4.z, qreg[4 * c + 2], a2);
                a3 = fmaf(h4.w, qreg[4 * c + 3], a3);
            }
            atomicAdd(&agg[dst * Hh + lane], (a0 + a1) + (a2 + a3));
        }
        __syncwarp();
    }
}

// ---------------------------------------------------------------------------
// layer-0 edge kernel: qreg built on the fly from 4 x-values and smem w2_0.
// ---------------------------------------------------------------------------
__global__ void __launch_bounds__(256, 4)
edge0_kernel(const float* __restrict__ x,
             const float* __restrict__ w1,
             const float* __restrict__ b1,
             const float* __restrict__ w2,
             const float* __restrict__ rbuf,
             float* __restrict__ agg) {
    __shared__ float w2s[Hh * Ff * Hh];        // 16KB
    __shared__ WarpTile wts[8];                // 8 x 4.375KB = 35KB
    const int wip  = threadIdx.x >> 5;
    const int n    = (blockIdx.x * blockDim.x + threadIdx.x) >> 5;
    const int lane = threadIdx.x & 31;

    for (int i = threadIdx.x; i < Hh * Ff * Hh; i += 256)
        w2s[i] = w2[i];
    __syncthreads();

    if (n >= Nn) return;
    const int beg = g_off[n], end = g_off[n + 1];
    if (beg == end) return;

    const float w1a = w1[lane], w1b = w1[Hh + lane], b1v = b1[lane];

    float x0 = x[n * Ff + 0], x1 = x[n * Ff + 1];
    float x2 = x[n * Ff + 2], x3 = x[n * Ff + 3];
    float qreg[Hh];
#pragma unroll
    for (int k = 0; k < Hh; k++) {
        const float* w = w2s + k * (Ff * Hh) + lane;
        qreg[k] = fmaf(x0, w[0], fmaf(x1, w[Hh],
                  fmaf(x2, w[2 * Hh], x3 * w[3 * Hh])));
    }
    const float rsrc = rbuf[n * Hh + lane];

    edge_loop(beg, end, lane, w1a, w1b, b1v, qreg, rsrc, &wts[wip], agg);
}

// ---------------------------------------------------------------------------
// fused Qn + aux (f32x2 FMA GEMM), layers 1-2 (din = 32)
// ---------------------------------------------------------------------------
template <int DIN>
__global__ void qnaux_kernel(const float* __restrict__ x,
                             const float* __restrict__ w2,
                             const float* __restrict__ root,
                             const float* __restrict__ bias,
                             const float* __restrict__ b2,
                             float* __restrict__ Qn,
                             float* __restrict__ agg,
                             float* __restrict__ rbuf) {
    __shared__ float2 xs2[8][DIN];
    const int nbase = blockIdx.x * 8;
    const int tid = threadIdx.x;

    for (int idx = tid; idx < 8 * DIN; idx += 128) {
        int t = idx / DIN, i = idx % DIN;
        float v = fmaxf(x[(nbase + t) * DIN + i], 0.f);   // relu on load
        xs2[t][i] = make_float2(v, v);
    }
    __syncthreads();

    const int c0 = tid * 8;
    const int k  = c0 >> 5;
    const int ob = c0 & 31;
    const float* wbase = w2 + k * (DIN * Hh) + ob;

    unsigned long long acc[8][4];
#pragma unroll
    for (int t = 0; t < 8; t++)
#pragma unroll
        for (int p = 0; p < 4; p++) acc[t][p] = 0ULL;

#pragma unroll
    for (int i = 0; i < DIN; i++) {
        ulonglong2 wa = *reinterpret_cast<const ulonglong2*>(wbase + i * Hh);
        ulonglong2 wb = *reinterpret_cast<const ulonglong2*>(wbase + i * Hh + 4);
#pragma unroll
        for (int t = 0; t < 8; t++) {
            unsigned long long xv =
                *reinterpret_cast<const unsigned long long*>(&xs2[t][i]);
            asm("fma.rn.f32x2 %0,%1,%2,%0;" : "+l"(acc[t][0]) : "l"(xv), "l"(wa.x));
            asm("fma.rn.f32x2 %0,%1,%2,%0;" : "+l"(acc[t][1]) : "l"(xv), "l"(wa.y));
            asm("fma.rn.f32x2 %0,%1,%2,%0;" : "+l"(acc[t][2]) : "l"(xv), "l"(wb.x));
            asm("fma.rn.f32x2 %0,%1,%2,%0;" : "+l"(acc[t][3]) : "l"(xv), "l"(wb.y));
        }
    }

#pragma unroll
    for (int t = 0; t < 8; t++) {
        float* dst = Qn + (nbase + t) * (Hh * Hh) + c0;
#pragma unroll
        for (int p = 0; p < 4; p++)
            *reinterpret_cast<unsigned long long*>(dst + p * 2) = acc[t][p];
    }

    for (int it = tid; it < 256; it += 128) {
        int t = it >> 5, o = it & 31;
        float accA = 0.f, accR = 0.f;
#pragma unroll
        for (int i = 0; i < DIN; i++) {
            float xv = xs2[t][i].x;
            accA = fmaf(xv, root[i * Hh + o], accA);
            accR = fmaf(xv, b2  [i * Hh + o], accR);
        }
        agg [(nbase + t) * Hh + o] = accA + bias[o];
        rbuf[(nbase + t) * Hh + o] = accR;
    }
}

// ---------------------------------------------------------------------------
// edge stage (layers 1-2): qreg loaded from precomputed Qn.
// ---------------------------------------------------------------------------
__global__ void __launch_bounds__(256, 4)
edge3_kernel(const float* __restrict__ w1,
             const float* __restrict__ b1,
             const float* __restrict__ Qn,
             const float* __restrict__ rbuf,
             float* __restrict__ agg) {
    __shared__ WarpTile wts[8];                // 35KB
    const int wip  = threadIdx.x >> 5;
    const int n    = (blockIdx.x * blockDim.x + threadIdx.x) >> 5;
    const int lane = threadIdx.x & 31;
    if (n >= Nn) return;
    const int beg = g_off[n], end = g_off[n + 1];
    if (beg == end) return;

    const float w1a = w1[lane], w1b = w1[Hh + lane], b1v = b1[lane];

    float qreg[Hh];
    const float* __restrict__ q = Qn + n * (Hh * Hh) + lane;
#pragma unroll
    for (int k = 0; k < Hh; k++) qreg[k] = q[k * Hh];
    const float rsrc = rbuf[n * Hh + lane];

    edge_loop(beg, end, lane, w1a, w1b, b1v, qreg, rsrc, &wts[wip], agg);
}

// ---------------------------------------------------------------------------
__global__ void fc_kernel(const float* __restrict__ xr,
                          const float* __restrict__ fcw,
                          const float* __restrict__ fcb,
                          float* __restrict__ out) {
    int warp = (blockIdx.x * blockDim.x + threadIdx.x) >> 5;
    int lane = threadIdx.x & 31;
    if (warp >= Nn) return;

    float xv = fmaxf(xr[warp * Hh + lane], 0.f);
    float lg[Cc];
#pragma unroll
    for (int c = 0; c < Cc; c++) {
        float p = xv * fcw[lane * Cc + c];
#pragma unroll
        for (int s = 16; s > 0; s >>= 1)
            p += __shfl_xor_sync(0xffffffffu, p, s);
        lg[c] = p + fcb[c];
    }
    float m = fmaxf(fmaxf(lg[0], lg[1]), fmaxf(lg[2], lg[3]));
    float se = 0.f;
#pragma unroll
    for (int c = 0; c < Cc; c++) se += __expf(lg[c] - m);
    float lse = m + __logf(se);
    if (lane < Cc) out[warp * Cc + lane] = lg[lane] - lse;
}

// ---------------------------------------------------------------------------
extern "C" void kernel_launch(void* const* d_in, const int* in_sizes, int n_in,
                              void* d_out, int out_size) {
    (void)in_sizes; (void)n_in; (void)out_size;

    const float* x  = (const float*)d_in[0];
    const int*   ei = (const int*)  d_in[1];
    const float* ea = (const float*)d_in[2];
    const float* w1[3];  const float* b1[3];  const float* w2[3];
    const float* b2[3];  const float* rt[3];  const float* bs[3];
    for (int l = 0; l < 3; l++) {
        w1[l] = (const float*)d_in[3 + 6 * l + 0];
        b1[l] = (const float*)d_in[3 + 6 * l + 1];
        w2[l] = (const float*)d_in[3 + 6 * l + 2];
        b2[l] = (const float*)d_in[3 + 6 * l + 3];
        rt[l] = (const float*)d_in[3 + 6 * l + 4];
        bs[l] = (const float*)d_in[3 + 6 * l + 5];
    }
    const float* fcw = (const float*)d_in[21];
    const float* fcb = (const float*)d_in[22];
    float* out = (float*)d_out;

    float *Qn, *rbuf, *xA, *xB;
    cudaGetSymbolAddress((void**)&Qn,   g_Qn);
    cudaGetSymbolAddress((void**)&rbuf, g_r);
    cudaGetSymbolAddress((void**)&xA,   g_xA);
    cudaGetSymbolAddress((void**)&xB,   g_xB);

    const int qnBlocks       = Nn / 8;                 // 1250
    const int nodeWarpBlocks = (Nn * 32 + 255) / 256;  // 1250
    const int e2Blocks       = (Ee / 2 + 255) / 256;   // 313

    // ---------------- counting sort of edges by src ---------------------
    zero_kernel<<<(Nn + 1023) / 1024, 1024>>>();
    hist_kernel<<<(Ee / 4 + 255) / 256, 256>>>(ei);
    scan_kernel<<<1, 1024>>>();
    scatter_kernel<<<e2Blocks, 256>>>(ei, ea);

    // ---------------- layer 0: Qn folded into the edge kernel -----------
    aux0_kernel<<<nodeWarpBlocks, 256>>>(x, rt[0], bs[0], b2[0], xA, rbuf);
    edge0_kernel<<<nodeWarpBlocks, 256>>>(x, w1[0], b1[0], w2[0], rbuf, xA);

    // ---------------- layer 1 -------------------------------------------
    qnaux_kernel<Hh><<<qnBlocks, 128>>>(xA, w2[1], rt[1], bs[1], b2[1], Qn, xB, rbuf);
    edge3_kernel<<<nodeWarpBlocks, 256>>>(w1[1], b1[1], Qn, rbuf, xB);

    // ---------------- layer 2 -------------------------------------------
    qnaux_kernel<Hh><<<qnBlocks, 128>>>(xB, w2[2], rt[2], bs[2], b2[2], Qn, xA, rbuf);
    edge3_kernel<<<nodeWarpBlocks, 256>>>(w1[2], b1[2], Qn, rbuf, xA);

    // ---------------- FC + log_softmax ----------------------------------
    fc_kernel<<<nodeWarpBlocks, 256>>>(xA, fcw, fcb, out);
}